// round 17
// baseline (speedup 1.0000x reference)
#include <cuda_runtime.h>
#include <cuda_bf16.h>
#include <cstdint>

#define S_LEN 512
#define B_DIM 64
#define I_DIM 512
#define H_DIM 1024
#define EPS_C 1e-10f
#define NB    128

typedef unsigned long long u64;

// ---------------- bf16 helpers ----------------
__device__ __forceinline__ void mma16(float* c, uint32_t a0, uint32_t a1, uint32_t a2, uint32_t a3,
                                      uint32_t b0, uint32_t b1) {
    asm volatile("mma.sync.aligned.m16n8k16.row.col.f32.bf16.bf16.f32 "
        "{%0,%1,%2,%3}, {%4,%5,%6,%7}, {%8,%9}, {%0,%1,%2,%3};"
        : "+f"(c[0]), "+f"(c[1]), "+f"(c[2]), "+f"(c[3])
        : "r"(a0), "r"(a1), "r"(a2), "r"(a3), "r"(b0), "r"(b1));
}
__device__ __forceinline__ uint32_t mulbf2(uint32_t a, uint32_t b) {
    uint32_t d; asm("mul.rn.bf16x2 %0, %1, %2;" : "=r"(d) : "r"(a), "r"(b)); return d;
}
__device__ __forceinline__ uint32_t bpack(float lo, float hi) {
    __nv_bfloat162 t = __floats2bfloat162_rn(lo, hi);   // .x = low half
    return *reinterpret_cast<uint32_t*>(&t);
}
__device__ __forceinline__ float tanh_ap(float x) {
    float y; asm("tanh.approx.f32 %0, %1;" : "=f"(y) : "f"(x)); return y;
}

// bf16 k16-group permutation: original j -> position; order [0,1,8,9,2,3,10,11,...]
__device__ __forceinline__ int kperm16(int j) {
    return (((j & 7) >> 1) << 2) | (((j >> 3) & 1) << 1) | (j & 1);
}

// ---------------- scoped atomics ----------------
__device__ __forceinline__ unsigned ld_acquire(const unsigned* p) {
    unsigned v;
    asm volatile("ld.acquire.gpu.u32 %0, [%1];" : "=r"(v) : "l"(p) : "memory");
    return v;
}
__device__ __forceinline__ void st_release(unsigned* p, unsigned v) {
    asm volatile("st.release.gpu.u32 [%0], %1;" :: "l"(p), "r"(v) : "memory");
}

// ---------------- device scratch ----------------
__device__ float g_mu_h[H_DIM * H_DIM];    // fp32, [k][n] (bf16 at scan staging)
__device__ float g_d_h [H_DIM * H_DIM];
// input-layer weights for warp-level xproj MMA: uint4 {mu(k0,k0+1),mu(k0+8,k0+9),
// d(k0,k0+1),d(k0+8,k0+9)}, index (c*4+tg)*1024 + n, k0 = c*16 + 2*tg
__device__ __align__(16) uint4 g_wxp[32 * 4 * 1024];
// x and x^2, bf16, PAIR-PACKED like h transport (per row, per k-128 group:
// element (chunk cl=2p+s, jp=kperm16(jj)) at g128*128 + p*32 + (jp>>2)*8 + s*4 + (jp&3))
__device__ __align__(16) __nv_bfloat16 g_xpp[S_LEN * B_DIM * I_DIM];
__device__ __align__(16) __nv_bfloat16 g_xqp[S_LEN * B_DIM * I_DIM];
// bf16 h transport, pair-packed (same scheme per k-eighth of 1024)
__device__ __align__(16) __nv_bfloat16 g_hA[B_DIM * H_DIM];
__device__ __align__(16) __nv_bfloat16 g_hB[B_DIM * H_DIM];
// release flags: g_flags[bid*32], one 128B line per block, monotonic
__device__ __align__(128) unsigned g_flags[NB * 32];
__device__ __align__(128) unsigned g_pflag[NB * 32];   // prologue-done flags

// ---------------- prep (weights + x transform fused) ----------------
__global__ void prep_kernel(const float* __restrict__ m_in, const float* __restrict__ pi_in,
                            const float* __restrict__ chi_in,
                            const float* __restrict__ m_h, const float* __restrict__ pi_h,
                            const float* __restrict__ chi_h,
                            const float* __restrict__ x)
{
    int idx = blockIdx.x * blockDim.x + threadIdx.x;
    int stride = gridDim.x * blockDim.x;

    for (int i = idx; i < H_DIM * H_DIM; i += stride) {
        float m = m_h[i], pi = pi_h[i], chi = chi_h[i];
        float mu = (1.0f - pi) * m;
        float rho = (1.0f - pi) * (chi + m * m);
        g_mu_h[i] = mu;
        g_d_h[i]  = rho - mu * mu;
    }
    // input weights -> g_wxp: i = (c*4+tg)*1024 + n
    for (int i = idx; i < 32 * 4 * 1024; i += stride) {
        int n  = i & 1023;
        int tg = (i >> 10) & 3;
        int c  = i >> 12;                   // k16-chunk 0..31
        int k0 = c * 16 + 2 * tg;
        int kk[4] = {k0, k0 + 1, k0 + 8, k0 + 9};
        float mv[4], dv[4];
#pragma unroll
        for (int j = 0; j < 4; j++) {
            int o = kk[j] * H_DIM + n;
            float m = m_in[o], pi = pi_in[o], chi = chi_in[o];
            float mu = (1.0f - pi) * m;
            mv[j] = mu;
            dv[j] = (1.0f - pi) * (chi + m * m) - mu * mu;
        }
        uint4 w;
        w.x = bpack(mv[0], mv[1]);
        w.y = bpack(mv[2], mv[3]);
        w.z = bpack(dv[0], dv[1]);
        w.w = bpack(dv[2], dv[3]);
        g_wxp[i] = w;
    }
    // x transform: bf16, pair-packed
    const int N = S_LEN * B_DIM * I_DIM;
    for (int i = idx; i < N; i += stride) {
        int k = i & (I_DIM - 1);
        int m = i >> 9;
        float v = x[i];
        int g128 = k >> 7, j = k & 127;
        int cl = j >> 4, jj = j & 15;
        int jp = kperm16(jj);
        int p = cl >> 1, s = cl & 1;
        int pos = g128 * 128 + p * 32 + (jp >> 2) * 8 + s * 4 + (jp & 3);
        int o = m * I_DIM + pos;
        g_xpp[o] = __float2bfloat16(v);
        g_xqp[o] = __float2bfloat16(v * v);
    }
    for (int i = idx; i < (B_DIM * H_DIM) / 2; i += stride)
        reinterpret_cast<uint32_t*>(g_hA)[i] = 0u;
    for (int i = idx; i < NB * 32; i += stride) {
        g_flags[i] = 0u;
        g_pflag[i] = 0u;
    }
}

// ---------------- warp-level xproj unit (K=64 slice of a 16x16 tile) ----------------
__device__ __forceinline__ void xproj_unit(int tp, int msub, int n0, int u,
                                           int half, int gid, int tig,
                                           float (&xG)[2][4], float (&xD)[2][4])
{
    const int rowA = tp * 64 + half * 32 + msub * 16 + gid;
    const size_t base = (size_t)rowA * I_DIM + (u >> 1) * 128 + (u & 1) * 64 + tig * 8;
    const __nv_bfloat16* xr0 = g_xpp + base;
    const __nv_bfloat16* xr1 = xr0 + 8 * I_DIM;
    const __nv_bfloat16* qr0 = g_xqp + base;
    const __nv_bfloat16* qr1 = qr0 + 8 * I_DIM;

    uint4 xa[2], xb[2], qa[2], qb[2];
#pragma unroll
    for (int l = 0; l < 2; l++) {
        xa[l] = __ldcg((const uint4*)(xr0 + l * 32));
        xb[l] = __ldcg((const uint4*)(xr1 + l * 32));
        qa[l] = __ldcg((const uint4*)(qr0 + l * 32));
        qb[l] = __ldcg((const uint4*)(qr1 + l * 32));
    }
#pragma unroll
    for (int l = 0; l < 2; l++) {
#pragma unroll
        for (int s = 0; s < 2; s++) {
            const int c = u * 4 + 2 * l + s;
            uint32_t a0 = s ? xa[l].z : xa[l].x;
            uint32_t a2 = s ? xa[l].w : xa[l].y;
            uint32_t a1 = s ? xb[l].z : xb[l].x;
            uint32_t a3 = s ? xb[l].w : xb[l].y;
            uint32_t q0 = s ? qa[l].z : qa[l].x;
            uint32_t q2 = s ? qa[l].w : qa[l].y;
            uint32_t q1 = s ? qb[l].z : qb[l].x;
            uint32_t q3 = s ? qb[l].w : qb[l].y;
#pragma unroll
            for (int ns = 0; ns < 2; ns++) {
                uint4 w = __ldg(&g_wxp[(c * 4 + tig) * 1024 + n0 + ns * 8 + gid]);
                mma16(xG[ns], a0, a1, a2, a3, w.x, w.y);
                mma16(xD[ns], q0, q1, q2, q3, w.z, w.w);
            }
        }
    }
}

__device__ __forceinline__ void xproj_epi(int tp, int msub, int n0,
                                          int half, int gid, int tig,
                                          float (&xG)[2][4], float (&xD)[2][4],
                                          const float* __restrict__ eps_in,
                                          float* __restrict__ out)
{
    const int rbase = tp * 64 + half * 32 + msub * 16 + gid;
#pragma unroll
    for (int ns = 0; ns < 2; ns++)
#pragma unroll
    for (int rh = 0; rh < 2; rh++) {
        int row = rbase + rh * 8;
        int col = n0 + ns * 8 + 2 * tig;
        size_t off = (size_t)row * H_DIM + col;
        float2 e = *(const float2*)(eps_in + off);
        float2 o;
        o.x = xG[ns][rh * 2]     + e.x * sqrtf(xD[ns][rh * 2]     + EPS_C);
        o.y = xG[ns][rh * 2 + 1] + e.y * sqrtf(xD[ns][rh * 2 + 1] + EPS_C);
        __stcg((float2*)(out + off), o);
    }
#pragma unroll
    for (int ns = 0; ns < 2; ns++)
#pragma unroll
    for (int q = 0; q < 4; q++) { xG[ns][q] = 0.0f; xD[ns][q] = 0.0f; }
}

// ---------------- persistent scan (R15 structure) + in-loop xproj ----------------
#define SC_SMEM (98304)

__global__ void __launch_bounds__(512, 1) scan_kernel(const float* __restrict__ eps_h,
                                                      const float* __restrict__ eps_in,
                                                      float* __restrict__ out,
                                                      int write_last)
{
    extern __shared__ char smc[];
    uint4* wpk = (uint4*)smc;                // [64 cg][4 tig][16 n] uint4 = 64KB
    float* pG = (float*)(smc + 65536);       // [8 ke][32 b][16 n] = 16KB
    float* pD = pG + 4096;

    const int tid  = threadIdx.x;
    const int warp = tid >> 5, lane = tid & 31;
    const int gid = lane >> 2, tig = lane & 3;
    const int n_base = (blockIdx.x >> 1) * 16;
    const int b_base = (blockIdx.x & 1) * 32;
    const int half = blockIdx.x & 1;
    const int mt = warp & 1, ke = warp >> 1;
    const int bid = blockIdx.x;

    // this warp's producer flag (lanes 0..7 each own one)
    unsigned* my_flag = &g_flags[(((ke * 8 + lane) * 2) + half) * 32];

    // xproj schedule: fixed per warp
    const int beta = bid >> 1;
    const int widx = beta * 16 + warp;       // 0..1023
    const int my_tl   = widx >> 7;           // 0..7
    const int my_msub = (widx >> 6) & 1;
    const int my_n0   = (widx & 63) * 16;

    // stage hidden weights once: mu and d single bf16, packed {mu01, mu89, d01, d89}
    for (int i = tid; i < 4096; i += 512) {
        int cg = i >> 6, tg = (i >> 4) & 3, n = i & 15;
        int sidx = cg * 64 + tg * 16 + ((n + 2 * tg) & 15);
        int k0 = cg * 16 + 2 * tg;
        int gn = n_base + n;
        float m0 = g_mu_h[(size_t)k0 * H_DIM + gn];
        float m1 = g_mu_h[(size_t)(k0 + 1) * H_DIM + gn];
        float m8 = g_mu_h[(size_t)(k0 + 8) * H_DIM + gn];
        float m9 = g_mu_h[(size_t)(k0 + 9) * H_DIM + gn];
        float d0 = g_d_h[(size_t)k0 * H_DIM + gn];
        float d1 = g_d_h[(size_t)(k0 + 1) * H_DIM + gn];
        float d8 = g_d_h[(size_t)(k0 + 8) * H_DIM + gn];
        float d9 = g_d_h[(size_t)(k0 + 9) * H_DIM + gn];
        uint4 w;
        w.x = bpack(m0, m1);
        w.y = bpack(m8, m9);
        w.z = bpack(d0, d1);
        w.w = bpack(d8, d9);
        wpk[sidx] = w;
    }
    __syncthreads();

    // hoist 4 of 8 nt=0 weight fragments (register budget shared with xproj accs)
    uint4 wreg[4];
#pragma unroll
    for (int c = 0; c < 4; c++)
        wreg[c] = wpk[(ke * 8 + c) * 64 + tig * 16 + ((gid + 2 * tig) & 15)];

    // xproj accumulators
    float xG[2][4] = {}, xD[2][4] = {};

    // ---- prologue: xproj for t' in [0,16): 2 tiles per warp ----
#pragma unroll 1
    for (int pid = 0; pid < 2; pid++) {
        int pidx = widx * 2 + pid;           // 0..2047
        int tpp = pidx >> 7;                 // 0..15
        int rem = pidx & 127;
        int pms = rem >> 6, pn0 = (rem & 63) * 16;
#pragma unroll 1
        for (int u = 0; u < 8; u++)
            xproj_unit(tpp, pms, pn0, u, half, gid, tig, xG, xD);
        xproj_epi(tpp, pms, pn0, half, gid, tig, xG, xD, eps_in, out);
    }
    __syncthreads();
    if (tid == 0) st_release(&g_pflag[bid * 32], 1u);
    if (tid < 64) {
        while (ld_acquire(&g_pflag[(tid * 2 + half) * 32]) < 1u) { }
    }
    __syncthreads();

    const int r0 = b_base + mt * 16 + gid;
    const int eb = tid >> 4;                 // 0..31
    const int en = tid & 15;                 // 0..15
    const int gbrow = b_base + eb;
    const int ncol = n_base + en;
    // pair-packed h transport offset
    const int cgB = n_base >> 4;
    const int keB = cgB >> 3;
    const int ccB = cgB & 7;
    const int ppB = ccB >> 1, ssB = ccB & 1;
    const int jp = kperm16(en);
    const int hoff = gbrow * H_DIM + keB * 128 + ppB * 32 + (jp >> 2) * 8 + ssB * 4 + (jp & 3);

    // prefetch step-0 epilogue operands (prologue barrier makes xproj[0] visible)
    size_t toff = (size_t)gbrow * H_DIM + ncol;
    float epre = __ldg(eps_h + toff);
    float xpre = __ldcg(out + toff);
    __syncthreads();

    for (int t = 0; t < S_LEN; t++) {
        const __nv_bfloat16* hsrc = (t & 1) ? g_hB : g_hA;
        __nv_bfloat16* hdst = (t & 1) ? g_hA : g_hB;

        // ---- per-warp producer gate (skip t=0: h0 preset by prep) ----
        if (t > 0) {
            if (lane < 8) {
                const unsigned tgt = (unsigned)t;
                while (ld_acquire(my_flag) < tgt) { }
            }
            __syncwarp();
        }

        // ---- preload h fragments: 8 independent LDG.128 (pair-packed) ----
        const __nv_bfloat16* hr0 = hsrc + (size_t)r0 * H_DIM + ke * 128 + tig * 8;
        const __nv_bfloat16* hr1 = hr0 + 8 * H_DIM;
        uint4 u0[4], u1[4];
#pragma unroll
        for (int p = 0; p < 4; p++) {
            u0[p] = __ldcg((const uint4*)(hr0 + p * 32));
            u1[p] = __ldcg((const uint4*)(hr1 + p * 32));
        }

        float cG[2][4] = {}, cD[2][4] = {};
#pragma unroll
        for (int p = 0; p < 4; p++) {
#pragma unroll
            for (int s = 0; s < 2; s++) {
                const int c = 2 * p + s;
                const int cg = ke * 8 + c;
                uint32_t a0 = s ? u0[p].z : u0[p].x;
                uint32_t a2 = s ? u0[p].w : u0[p].y;
                uint32_t a1 = s ? u1[p].z : u1[p].x;
                uint32_t a3 = s ? u1[p].w : u1[p].y;
                uint32_t q0 = mulbf2(a0, a0), q2 = mulbf2(a2, a2);
                uint32_t q1 = mulbf2(a1, a1), q3 = mulbf2(a3, a3);
                uint4 w0 = (c < 4) ? wreg[c & 3]
                                   : wpk[cg * 64 + tig * 16 + ((gid + 2 * tig) & 15)];
                mma16(cG[0], a0, a1, a2, a3, w0.x, w0.y);
                mma16(cD[0], q0, q1, q2, q3, w0.z, w0.w);
                uint4 w1 = wpk[cg * 64 + tig * 16 + ((8 + gid + 2 * tig) & 15)];
                mma16(cG[1], a0, a1, a2, a3, w1.x, w1.y);
                mma16(cD[1], q0, q1, q2, q3, w1.z, w1.w);
            }
        }

        // partials -> psum
        const int rowa = ke * 32 + mt * 16 + gid;
#pragma unroll
        for (int nt = 0; nt < 2; nt++) {
            int colb = nt * 8 + tig * 2;
            *(float2*)&pG[rowa * 16 + colb]       = make_float2(cG[nt][0], cG[nt][1]);
            *(float2*)&pG[(rowa + 8) * 16 + colb] = make_float2(cG[nt][2], cG[nt][3]);
            *(float2*)&pD[rowa * 16 + colb]       = make_float2(cD[nt][0], cD[nt][1]);
            *(float2*)&pD[(rowa + 8) * 16 + colb] = make_float2(cD[nt][2], cD[nt][3]);
        }
        __syncthreads();

        // reduce 8 k-slices + epilogue (1 output per thread)
        float G = 0.0f, D = 0.0f;
#pragma unroll
        for (int q = 0; q < 8; q++) {
            G += pG[(q * 32 + eb) * 16 + en];
            D += pD[(q * 32 + eb) * 16 + en];
        }
        float h = tanh_ap(G + epre * sqrtf(D + EPS_C) + xpre);
        hdst[hoff] = __float2bfloat16(h);    // h transport: the only critical store

        if (t == S_LEN - 1) {
            out[toff] = h;
            if (write_last)
                out[(size_t)S_LEN * B_DIM * H_DIM + gbrow * H_DIM + ncol] = h;
            break;
        }

        // ---- release: all block h stores done -> publish flag ----
        __syncthreads();                      // h stores + psum reads complete
        if (tid == 0)
            st_release(&g_flags[bid * 32], (unsigned)(t + 1));

        // hidden work: out-store, next-step prefetch, xproj duty slice
        out[toff] = h;
        toff = (size_t)((t + 1) * B_DIM + gbrow) * H_DIM + ncol;
        epre = __ldg(eps_h + toff);
        xpre = __ldcg(out + toff);

        {
            const int u = t & 7;
            const int tp = 16 + (t & ~7) + my_tl;
            if (tp < S_LEN) {
                xproj_unit(tp, my_msub, my_n0, u, half, gid, tig, xG, xD);
                if (u == 7)
                    xproj_epi(tp, my_msub, my_n0, half, gid, tig, xG, xD, eps_in, out);
            }
        }
    }
}

// ---------------- launch ----------------
extern "C" void kernel_launch(void* const* d_in, const int* in_sizes, int n_in,
                              void* d_out, int out_size)
{
    (void)in_sizes; (void)n_in;
    const float* x      = (const float*)d_in[0];
    const float* eps_in = (const float*)d_in[1];
    const float* eps_h  = (const float*)d_in[2];
    const float* m_in   = (const float*)d_in[3];
    const float* pi_in  = (const float*)d_in[4];
    const float* chi_in = (const float*)d_in[5];
    const float* m_h    = (const float*)d_in[6];
    const float* pi_h   = (const float*)d_in[7];
    const float* chi_h  = (const float*)d_in[8];
    float* out = (float*)d_out;

    prep_kernel<<<2048, 256>>>(m_in, pi_in, chi_in, m_h, pi_h, chi_h, x);

    cudaFuncSetAttribute(scan_kernel, cudaFuncAttributeMaxDynamicSharedMemorySize, SC_SMEM);
    int write_last = (out_size >= S_LEN * B_DIM * H_DIM + B_DIM * H_DIM) ? 1 : 0;
    scan_kernel<<<NB, 512, SC_SMEM>>>(eps_h, eps_in, out, write_last);
}